// round 16
// baseline (speedup 1.0000x reference)
#include <cuda_runtime.h>
#include <cuda_fp16.h>
#include <cstdint>
#include <cstddef>

// ---------------- problem constants ----------------
static constexpr int GQ   = 8;
static constexpr int HDIM = 4096;
static constexpr int IDIM = 1536;
static constexpr int MTOT = 16384;
static constexpr int MG   = MTOT / GQ;        // 2048

// ---------------- tiling (R8: proven floor shape) ----------------
static constexpr int TILE_M = 128;
static constexpr int TILE_J = 128;
static constexpr int BROWS  = 2 * TILE_J;     // 256 w-rows (gate/up interleaved)
static constexpr int TILE_K = 64;             // fp16 -> 128B rows
static constexpr int STAGES = 4;
static constexpr int NITER  = HDIM / TILE_K;  // 64
static constexpr int MT     = MG / TILE_M;    // 16
static constexpr int NT     = IDIM / TILE_J;  // 12
static constexpr int NTILES = GQ * MT * NT;   // 1536

// producer/consumer overlap
static constexpr int NCVT  = 64;              // converter CTAs (wave-1 co-resident)
static constexpr int NSLAB = NITER;           // 64 k-slabs
// NFULL: wave1 has 148-NCVT=84 fulls; remaining 1332 = 9*148 exactly
static constexpr int NSPLIT = 120;            // tail tiles -> 240 half-K CTAs
static constexpr int NFULL  = NTILES - NSPLIT;            // 1416 = 84 + 9*148
static constexpr int ACC_N  = 128;

static constexpr int A_BYTES     = TILE_M * TILE_K * 2;   // 16 KB
static constexpr int B_BYTES     = BROWS  * TILE_K * 2;   // 32 KB
static constexpr int STAGE_BYTES = A_BYTES + B_BYTES;     // 48 KB
static constexpr int SMEM_TOTAL  = STAGES * STAGE_BYTES;  // 192 KB
static constexpr int THREADS     = 256;

// ---------------- scratch ----------------
__device__ __half   g_xh[(size_t)MTOT * HDIM];                     // 128 MB
__device__ __half   g_wh[(size_t)GQ * 2 * IDIM * HDIM];            // 192 MB
__device__ float    g_part[(size_t)2 * NSPLIT * THREADS * ACC_N];  // 31.5 MB
__device__ unsigned g_flag[NSLAB];                                  // slab-ready counters

// ---------------- PTX helpers ----------------
__device__ __forceinline__ uint32_t smem_u32(const void* p) {
    uint32_t a;
    asm("{ .reg .u64 t; cvta.to.shared.u64 t, %1; cvt.u32.u64 %0, t; }" : "=r"(a) : "l"(p));
    return a;
}
__device__ __forceinline__ void cp_async16(uint32_t dst, const void* src) {
    asm volatile("cp.async.cg.shared.global [%0], [%1], 16;" :: "r"(dst), "l"(src));
}
__device__ __forceinline__ void cp_commit() {
    asm volatile("cp.async.commit_group;" ::: "memory");
}
__device__ __forceinline__ void cp_wait1() {
    asm volatile("cp.async.wait_group 1;" ::: "memory");
}
__device__ __forceinline__ void ldsm4(uint32_t* r, uint32_t addr) {
    asm("ldmatrix.sync.aligned.m8n8.x4.shared.b16 {%0,%1,%2,%3}, [%4];"
        : "=r"(r[0]), "=r"(r[1]), "=r"(r[2]), "=r"(r[3]) : "r"(addr) : "memory");
}
__device__ __forceinline__ void mma16(float* d, const uint32_t* a, uint32_t b0, uint32_t b1) {
    asm("mma.sync.aligned.m16n8k16.row.col.f32.f16.f16.f32 "
        "{%0,%1,%2,%3}, {%4,%5,%6,%7}, {%8,%9}, {%0,%1,%2,%3};"
        : "+f"(d[0]), "+f"(d[1]), "+f"(d[2]), "+f"(d[3])
        : "r"(a[0]), "r"(a[1]), "r"(a[2]), "r"(a[3]), "r"(b0), "r"(b1));
}
__device__ __forceinline__ float silu_mul(float g, float u) {
    return g * u / (1.0f + __expf(-g));
}
__device__ __forceinline__ unsigned ld_acq(const unsigned* p) {
    unsigned v;
    asm volatile("ld.acquire.gpu.u32 %0, [%1];" : "=r"(v) : "l"(p) : "memory");
    return v;
}
// spin until slab s ready; return new watermark (NSLAB if everything done)
__device__ __forceinline__ unsigned wait_slab(int s) {
    while (ld_acq(&g_flag[s]) < (unsigned)NCVT) { }
    if (ld_acq(&g_flag[NSLAB - 1]) >= (unsigned)NCVT) return (unsigned)NSLAB;
    return (unsigned)(s + 1);
}

// ---------------- flag reset (per replay) ----------------
__global__ void zero_flags_kernel() {
    g_flag[threadIdx.x] = 0u;
}

// ---------------- mega: 64 converter CTAs + 1416 full-tile CTAs ----------------
__global__ void __launch_bounds__(THREADS, 1)
swiglu_mega(const float4* __restrict__ x32, const float4* __restrict__ w32,
            __half* xh_w, __half* wh_w,
            const __half* __restrict__ x, const __half* __restrict__ w,
            float* __restrict__ out) {
    const int bx  = blockIdx.x;
    const int tid = threadIdx.x;

    if (bx < NCVT) {
        // ---- converter role: k-slab-ordered fp32 -> fp16, release flag per slab ----
        #pragma unroll 1
        for (int s = 0; s < NSLAB; ++s) {
            // x slab share: 16 float4 per thread (2 batches of 8, MLP=8)
            #pragma unroll 1
            for (int b = 0; b < 2; ++b) {
                float4 v[8];
                #pragma unroll
                for (int q = 0; q < 8; ++q) {
                    const int idx = bx * 4096 + (b * 8 + q) * 256 + tid;
                    v[q] = __ldcs(&x32[(size_t)(idx >> 4) * 1024 + s * 16 + (idx & 15)]);
                }
                #pragma unroll
                for (int q = 0; q < 8; ++q) {
                    const int idx = bx * 4096 + (b * 8 + q) * 256 + tid;
                    const int row = idx >> 4, j = idx & 15;
                    __half2 lo = __floats2half2_rn(v[q].x, v[q].y);
                    __half2 hi = __floats2half2_rn(v[q].z, v[q].w);
                    uint2 pk;
                    pk.x = *reinterpret_cast<uint32_t*>(&lo);
                    pk.y = *reinterpret_cast<uint32_t*>(&hi);
                    __stcs(reinterpret_cast<uint2*>(xh_w + (size_t)row * 4096 + s * 64 + j * 4), pk);
                }
            }
            // w slab share: 24 float4 per thread (3 batches of 8)
            #pragma unroll 1
            for (int b = 0; b < 3; ++b) {
                float4 v[8];
                #pragma unroll
                for (int q = 0; q < 8; ++q) {
                    const int idx = bx * 6144 + (b * 8 + q) * 256 + tid;
                    v[q] = __ldcs(&w32[(size_t)(idx >> 4) * 1024 + s * 16 + (idx & 15)]);
                }
                #pragma unroll
                for (int q = 0; q < 8; ++q) {
                    const int idx = bx * 6144 + (b * 8 + q) * 256 + tid;
                    const int row = idx >> 4, j = idx & 15;
                    __half2 lo = __floats2half2_rn(v[q].x, v[q].y);
                    __half2 hi = __floats2half2_rn(v[q].z, v[q].w);
                    uint2 pk;
                    pk.x = *reinterpret_cast<uint32_t*>(&lo);
                    pk.y = *reinterpret_cast<uint32_t*>(&hi);
                    __stcs(reinterpret_cast<uint2*>(wh_w + (size_t)row * 4096 + s * 64 + j * 4), pk);
                }
            }
            __threadfence();        // publish all this thread's stores
            __syncthreads();        // all threads of CTA done + fenced
            if (tid == 0) atomicAdd(&g_flag[s], 1u);
        }
        return;
    }

    // ---- full-tile role (R15 hot path + watermark flag poll) ----
    extern __shared__ char smem[];
    const uint32_t sb = smem_u32(smem);

    const int lane = tid & 31;
    const int wid  = tid >> 5;
    const int wm   = wid >> 2;
    const int wn   = wid & 3;

    const int tix = bx - NCVT;           // 0..NFULL-1
    const int g   = tix / (MT * NT);
    const int r2  = tix % (MT * NT);
    const int mt  = r2 / NT;
    const int nt  = r2 % NT;

    const size_t m0 = (size_t)g * MG + (size_t)mt * TILE_M;
    const int    n0 = nt * TILE_J;

    const __half* Ax = x + m0 * HDIM;
    const __half* Wg = w + ((size_t)g * (2 * IDIM) + (size_t)n0) * HDIM;

    uint32_t dA[4], oA[4];
    #pragma unroll
    for (int t = 0; t < 4; ++t) {
        const int c = tid + THREADS * t;
        const int m = c >> 3, s = c & 7;
        dA[t] = (uint32_t)((((m >> 3) * 8 + s) << 7) + (((m & 7) ^ s) << 4));
        oA[t] = (uint32_t)(m * HDIM + s * 8);
    }
    uint32_t dB[8], oB[8];
    #pragma unroll
    for (int t = 0; t < 8; ++t) {
        const int c  = tid + THREADS * t;
        const int rr = c >> 3, s = c & 7;
        const int j  = rr >> 1;
        dB[t] = (uint32_t)(A_BYTES + (((rr >> 3) * 8 + s) << 7) + (((rr & 7) ^ s) << 4));
        oB[t] = (uint32_t)(j * HDIM + s * 8 + ((rr & 1) ? IDIM * HDIM : 0));
    }

    const int quad = lane >> 3;
    const int row  = lane & 7;
    const uint32_t mterm0 = (uint32_t)((wm * 8 + (quad & 1)) << 10);
    uint32_t ktA[4];
    #pragma unroll
    for (int ks = 0; ks < 4; ++ks) {
        const int kb = 2 * ks + (quad >> 1);
        ktA[ks] = (uint32_t)((kb << 7) + ((row ^ kb) << 4));
    }
    const uint32_t nterm0 = (uint32_t)(A_BYTES + ((wn * 8 + (quad >> 1)) << 10));
    uint32_t ktB[4];
    #pragma unroll
    for (int ks = 0; ks < 4; ++ks) {
        const int kb = 2 * ks + (quad & 1);
        ktB[ks] = (uint32_t)((kb << 7) + ((row ^ kb) << 4));
    }

    float acc[ACC_N];
    #pragma unroll
    for (int i = 0; i < ACC_N; ++i) acc[i] = 0.0f;

    // watermark: if all slabs converted (waves >= 2), never poll again
    unsigned rdy = (ld_acq(&g_flag[NSLAB - 1]) >= (unsigned)NCVT) ? (unsigned)NSLAB : 0u;

    #pragma unroll
    for (int s = 0; s < STAGES - 1; ++s) {
        if ((unsigned)s >= rdy) rdy = wait_slab(s);
        const uint32_t st = sb + (uint32_t)(s * STAGE_BYTES);
        const __half* a = Ax + s * TILE_K;
        const __half* b = Wg + s * TILE_K;
        #pragma unroll
        for (int t = 0; t < 4; ++t) cp_async16(st + dA[t], a + oA[t]);
        #pragma unroll
        for (int t = 0; t < 8; ++t) cp_async16(st + dB[t], b + oB[t]);
        cp_commit();
    }

    #pragma unroll 1
    for (int i = 0; i < NITER; ++i) {
        cp_wait1();
        __syncthreads();

        if (i + STAGES - 1 < NITER) {
            const int it = i + STAGES - 1;
            if ((unsigned)it >= rdy) rdy = wait_slab(it);
            const uint32_t stw = sb + (uint32_t)((it & 3) * STAGE_BYTES);
            const __half* a = Ax + it * TILE_K;
            const __half* b = Wg + it * TILE_K;
            #pragma unroll
            for (int t = 0; t < 4; ++t) cp_async16(stw + dA[t], a + oA[t]);
            #pragma unroll
            for (int t = 0; t < 8; ++t) cp_async16(stw + dB[t], b + oB[t]);
        }
        cp_commit();

        const uint32_t st = sb + (uint32_t)((i & 3) * STAGE_BYTES);
        #pragma unroll
        for (int ks = 0; ks < 4; ++ks) {
            uint32_t afr[16], bfr[16];
            #pragma unroll
            for (int f = 0; f < 4; ++f)
                ldsm4(&afr[4 * f], st + mterm0 + (uint32_t)(f << 11) + ktA[ks]);
            #pragma unroll
            for (int gg = 0; gg < 4; ++gg)
                ldsm4(&bfr[4 * gg], st + nterm0 + (uint32_t)(gg << 11) + ktB[ks]);
            #pragma unroll
            for (int f = 0; f < 4; ++f) {
                #pragma unroll
                for (int nf = 0; nf < 8; ++nf) {
                    const int bo = ((nf >> 1) << 2) + ((nf & 1) << 1);
                    mma16(&acc[(f * 8 + nf) * 4], &afr[4 * f], bfr[bo], bfr[bo + 1]);
                }
            }
        }
    }

    __syncthreads();

    const int gid = lane >> 2;
    const int tg  = lane & 3;
    #pragma unroll
    for (int f = 0; f < 4; ++f) {
        #pragma unroll
        for (int nf = 0; nf < 8; ++nf) {
            const float* c = &acc[(f * 8 + nf) * 4];
            const size_t mg1 = m0 + (size_t)(wm * 64 + f * 16 + gid);
            const int    jg  = n0 + wn * 32 + nf * 4 + tg;
            out[mg1 * IDIM + jg]       = silu_mul(c[0], c[1]);
            out[(mg1 + 8) * IDIM + jg] = silu_mul(c[2], c[3]);
        }
    }
}

// ---------------- TAIL: half-K CTAs for the last NSPLIT tiles (runs after mega) ----------------
static constexpr int TITER = NITER / 2;       // 32

__global__ void __launch_bounds__(THREADS, 1)
swiglu_tail(const __half* __restrict__ x, const __half* __restrict__ w) {
    extern __shared__ char smem[];
    const uint32_t sb = smem_u32(smem);

    const int tid  = threadIdx.x;
    const int lane = tid & 31;
    const int wid  = tid >> 5;
    const int wm   = wid >> 2;
    const int wn   = wid & 3;

    const int sp      = blockIdx.x;      // 0..2*NSPLIT-1
    const int tileIdx = NFULL + (sp >> 1);
    const int k0      = (sp & 1) * TITER;

    const int g  = tileIdx / (MT * NT);
    const int r2 = tileIdx % (MT * NT);
    const int mt = r2 / NT;
    const int nt = r2 % NT;

    const size_t m0 = (size_t)g * MG + (size_t)mt * TILE_M;
    const int    n0 = nt * TILE_J;

    const __half* Ax = x + m0 * HDIM + (size_t)k0 * TILE_K;
    const __half* Wg = w + ((size_t)g * (2 * IDIM) + (size_t)n0) * HDIM + (size_t)k0 * TILE_K;

    uint32_t dA[4], oA[4];
    #pragma unroll
    for (int t = 0; t < 4; ++t) {
        const int c = tid + THREADS * t;
        const int m = c >> 3, s = c & 7;
        dA[t] = (uint32_t)((((m >> 3) * 8 + s) << 7) + (((m & 7) ^ s) << 4));
        oA[t] = (uint32_t)(m * HDIM + s * 8);
    }
    uint32_t dB[8], oB[8];
    #pragma unroll
    for (int t = 0; t < 8; ++t) {
        const int c  = tid + THREADS * t;
        const int rr = c >> 3, s = c & 7;
        const int j  = rr >> 1;
        dB[t] = (uint32_t)(A_BYTES + (((rr >> 3) * 8 + s) << 7) + (((rr & 7) ^ s) << 4));
        oB[t] = (uint32_t)(j * HDIM + s * 8 + ((rr & 1) ? IDIM * HDIM : 0));
    }

    const int quad = lane >> 3;
    const int row  = lane & 7;
    const uint32_t mterm0 = (uint32_t)((wm * 8 + (quad & 1)) << 10);
    uint32_t ktA[4];
    #pragma unroll
    for (int ks = 0; ks < 4; ++ks) {
        const int kb = 2 * ks + (quad >> 1);
        ktA[ks] = (uint32_t)((kb << 7) + ((row ^ kb) << 4));
    }
    const uint32_t nterm0 = (uint32_t)(A_BYTES + ((wn * 8 + (quad >> 1)) << 10));
    uint32_t ktB[4];
    #pragma unroll
    for (int ks = 0; ks < 4; ++ks) {
        const int kb = 2 * ks + (quad & 1);
        ktB[ks] = (uint32_t)((kb << 7) + ((row ^ kb) << 4));
    }

    float acc[ACC_N];
    #pragma unroll
    for (int i = 0; i < ACC_N; ++i) acc[i] = 0.0f;

    #pragma unroll
    for (int s = 0; s < STAGES - 1; ++s) {
        const uint32_t st = sb + (uint32_t)(s * STAGE_BYTES);
        const __half* a = Ax + s * TILE_K;
        const __half* b = Wg + s * TILE_K;
        #pragma unroll
        for (int t = 0; t < 4; ++t) cp_async16(st + dA[t], a + oA[t]);
        #pragma unroll
        for (int t = 0; t < 8; ++t) cp_async16(st + dB[t], b + oB[t]);
        cp_commit();
    }

    #pragma unroll 1
    for (int i = 0; i < TITER; ++i) {
        cp_wait1();
        __syncthreads();

        if (i + STAGES - 1 < TITER) {
            const int it = i + STAGES - 1;
            const uint32_t stw = sb + (uint32_t)((it & 3) * STAGE_BYTES);
            const __half* a = Ax + it * TILE_K;
            const __half* b = Wg + it * TILE_K;
            #pragma unroll
            for (int t = 0; t < 4; ++t) cp_async16(stw + dA[t], a + oA[t]);
            #pragma unroll
            for (int t = 0; t < 8; ++t) cp_async16(stw + dB[t], b + oB[t]);
        }
        cp_commit();

        const uint32_t st = sb + (uint32_t)((i & 3) * STAGE_BYTES);
        #pragma unroll
        for (int ks = 0; ks < 4; ++ks) {
            uint32_t afr[16], bfr[16];
            #pragma unroll
            for (int f = 0; f < 4; ++f)
                ldsm4(&afr[4 * f], st + mterm0 + (uint32_t)(f << 11) + ktA[ks]);
            #pragma unroll
            for (int gg = 0; gg < 4; ++gg)
                ldsm4(&bfr[4 * gg], st + nterm0 + (uint32_t)(gg << 11) + ktB[ks]);
            #pragma unroll
            for (int f = 0; f < 4; ++f) {
                #pragma unroll
                for (int nf = 0; nf < 8; ++nf) {
                    const int bo = ((nf >> 1) << 2) + ((nf & 1) << 1);
                    mma16(&acc[(f * 8 + nf) * 4], &afr[4 * f], bfr[bo], bfr[bo + 1]);
                }
            }
        }
    }

    __syncthreads();

    float* dst = g_part + ((size_t)(sp & 1) * NSPLIT + (size_t)(sp >> 1)) *
                         (THREADS * ACC_N) + (size_t)tid * ACC_N;
    #pragma unroll
    for (int i = 0; i < ACC_N; ++i) dst[i] = acc[i];
}

// ---------------- combine: flat, coalesced (R15-proven) ----------------
static constexpr int PAIRS_PER_TILE = THREADS * ACC_N / 2;   // 16384
static constexpr int NPAIRS = NSPLIT * PAIRS_PER_TILE;       // 1966080

__global__ void __launch_bounds__(256, 1)
combine_kernel(float* __restrict__ out) {
    const int j = blockIdx.x * 256 + threadIdx.x;
    if (j >= NPAIRS) return;

    const int sp2 = j >> 14;
    const int rem = j & (PAIRS_PER_TILE - 1);
    const int tid = rem >> 6;
    const int a   = rem & 63;

    const size_t off = (size_t)sp2 * (THREADS * ACC_N) + (size_t)tid * ACC_N + 2 * a;
    const float2 v0 = *reinterpret_cast<const float2*>(g_part + off);
    const float2 v1 = *reinterpret_cast<const float2*>(
        g_part + (size_t)NSPLIT * (THREADS * ACC_N) + off);
    const float gv = v0.x + v1.x;
    const float uv = v0.y + v1.y;

    const int lane = tid & 31, wid = tid >> 5;
    const int wm = wid >> 2, wn = wid & 3;
    const int gid = lane >> 2, tg = lane & 3;
    const int half = a & 1, fn = a >> 1;
    const int f = fn >> 3, nf = fn & 7;

    const int tileIdx = NFULL + sp2;
    const int g  = tileIdx / (MT * NT);
    const int r2 = tileIdx % (MT * NT);
    const int mt = r2 / NT;
    const int nt = r2 % NT;
    const size_t m0 = (size_t)g * MG + (size_t)mt * TILE_M;
    const int    n0 = nt * TILE_J;

    const size_t mg1 = m0 + (size_t)(wm * 64 + f * 16 + gid + half * 8);
    const int    jg  = n0 + wn * 32 + nf * 4 + tg;
    out[mg1 * IDIM + jg] = silu_mul(gv, uv);
}

// ---------------- launch ----------------
extern "C" void kernel_launch(void* const* d_in, const int* in_sizes, int n_in,
                              void* d_out, int out_size) {
    const float* x = (const float*)d_in[0];
    const float* w = (const float*)d_in[1];
    float* out = (float*)d_out;

    void* pxh = nullptr;
    void* pwh = nullptr;
    cudaGetSymbolAddress(&pxh, g_xh);
    cudaGetSymbolAddress(&pwh, g_wh);

    cudaFuncSetAttribute(swiglu_mega,
                         cudaFuncAttributeMaxDynamicSharedMemorySize, SMEM_TOTAL);
    cudaFuncSetAttribute(swiglu_tail,
                         cudaFuncAttributeMaxDynamicSharedMemorySize, SMEM_TOTAL);

    zero_flags_kernel<<<1, NSLAB>>>();
    swiglu_mega<<<NCVT + NFULL, THREADS, SMEM_TOTAL>>>(
        (const float4*)x, (const float4*)w,
        (__half*)pxh, (__half*)pwh,
        (const __half*)pxh, (const __half*)pwh, out);
    swiglu_tail<<<2 * NSPLIT, THREADS, SMEM_TOTAL>>>(
        (const __half*)pxh, (const __half*)pwh);
    combine_kernel<<<(NPAIRS + 255) / 256, 256>>>(out);
}

// round 17
// speedup vs baseline: 1.1246x; 1.1246x over previous
#include <cuda_runtime.h>
#include <cuda_fp16.h>
#include <cstdint>
#include <cstddef>

// ---------------- problem constants ----------------
static constexpr int GQ   = 8;
static constexpr int HDIM = 4096;
static constexpr int IDIM = 1536;
static constexpr int MTOT = 16384;
static constexpr int MG   = MTOT / GQ;        // 2048

// ---------------- tiling (R8: proven floor shape) ----------------
static constexpr int TILE_M = 128;
static constexpr int TILE_J = 128;
static constexpr int BROWS  = 2 * TILE_J;     // 256 w-rows (gate/up interleaved)
static constexpr int TILE_K = 64;             // fp16 -> 128B rows
static constexpr int STAGES = 4;
static constexpr int NITER  = HDIM / TILE_K;  // 64
static constexpr int MT     = MG / TILE_M;    // 16
static constexpr int NT     = IDIM / TILE_J;  // 12
static constexpr int NTILES = GQ * MT * NT;   // 1536

static constexpr int NSPLIT = 56;             // tail tiles (1536 - 148*10)
static constexpr int NFULL  = NTILES - NSPLIT;            // 1480 = 148*10
static constexpr int ACC_N  = 128;

static constexpr int A_BYTES     = TILE_M * TILE_K * 2;   // 16 KB
static constexpr int B_BYTES     = BROWS  * TILE_K * 2;   // 32 KB
static constexpr int STAGE_BYTES = A_BYTES + B_BYTES;     // 48 KB
static constexpr int SMEM_TOTAL  = STAGES * STAGE_BYTES;  // 192 KB
static constexpr int THREADS     = 256;                   // 8 warps: 2m x 4n

// ---------------- scratch ----------------
__device__ __half g_xh[(size_t)MTOT * HDIM];                       // 128 MB
__device__ __half g_wh[(size_t)GQ * 2 * IDIM * HDIM];              // 192 MB
__device__ float  g_part[(size_t)2 * NSPLIT * THREADS * ACC_N];    // 14.7 MB

// ---------------- PTX helpers (base sm_103: no tcgen05) ----------------
__device__ __forceinline__ uint32_t smem_u32(const void* p) {
    uint32_t a;
    asm("{ .reg .u64 t; cvta.to.shared.u64 t, %1; cvt.u32.u64 %0, t; }" : "=r"(a) : "l"(p));
    return a;
}
__device__ __forceinline__ void cp_async16(uint32_t dst, const void* src) {
    asm volatile("cp.async.cg.shared.global [%0], [%1], 16;" :: "r"(dst), "l"(src));
}
__device__ __forceinline__ void cp_commit() {
    asm volatile("cp.async.commit_group;" ::: "memory");
}
__device__ __forceinline__ void cp_wait1() {
    asm volatile("cp.async.wait_group 1;" ::: "memory");
}
__device__ __forceinline__ void ldsm4(uint32_t* r, uint32_t addr) {
    asm("ldmatrix.sync.aligned.m8n8.x4.shared.b16 {%0,%1,%2,%3}, [%4];"
        : "=r"(r[0]), "=r"(r[1]), "=r"(r[2]), "=r"(r[3]) : "r"(addr) : "memory");
}
__device__ __forceinline__ void mma16(float* d, const uint32_t* a, uint32_t b0, uint32_t b1) {
    asm("mma.sync.aligned.m16n8k16.row.col.f32.f16.f16.f32 "
        "{%0,%1,%2,%3}, {%4,%5,%6,%7}, {%8,%9}, {%0,%1,%2,%3};"
        : "+f"(d[0]), "+f"(d[1]), "+f"(d[2]), "+f"(d[3])
        : "r"(a[0]), "r"(a[1]), "r"(a[2]), "r"(a[3]), "r"(b0), "r"(b1));
}
__device__ __forceinline__ float silu_mul(float g, float u) {
    return g * u / (1.0f + __expf(-g));
}

// ---------------- prepass: fp32 -> fp16 (RN), 8 floats/thread, 16B stores ----------------
static constexpr size_t NX  = (size_t)MTOT * HDIM;                 // 67.1M floats
static constexpr size_t NW  = (size_t)GQ * 2 * IDIM * HDIM;        // 100.7M floats
static constexpr int    NX8 = (int)(NX / 8);                       // 8.39M
static constexpr int    NT8 = (int)((NX + NW) / 8);                // 20.97M

__global__ void cvt_f16_kernel(const float4* __restrict__ x, __half* __restrict__ xh,
                               const float4* __restrict__ w, __half* __restrict__ wh) {
    const int j = blockIdx.x * 256 + threadIdx.x;      // one 8-float chunk per thread
    const float4* src;
    __half* dst;
    if (j < NX8) { src = x + 2 * (size_t)j;          dst = xh + (size_t)j * 8; }
    else         { src = w + 2 * (size_t)(j - NX8);  dst = wh + (size_t)(j - NX8) * 8; }
    const float4 v0 = __ldcs(src);
    const float4 v1 = __ldcs(src + 1);
    __half2 h0 = __floats2half2_rn(v0.x, v0.y);
    __half2 h1 = __floats2half2_rn(v0.z, v0.w);
    __half2 h2 = __floats2half2_rn(v1.x, v1.y);
    __half2 h3 = __floats2half2_rn(v1.z, v1.w);
    uint4 pk;
    pk.x = *reinterpret_cast<uint32_t*>(&h0);
    pk.y = *reinterpret_cast<uint32_t*>(&h1);
    pk.z = *reinterpret_cast<uint32_t*>(&h2);
    pk.w = *reinterpret_cast<uint32_t*>(&h3);
    __stcs(reinterpret_cast<uint4*>(dst), pk);
}

// ---------------- FULL kernel: byte-identical R8 hot path, grid = 1480 ----------------
__global__ void __launch_bounds__(THREADS, 1)
swiglu_full(const __half* __restrict__ x, const __half* __restrict__ w,
            float* __restrict__ out) {
    extern __shared__ char smem[];
    const uint32_t sb = smem_u32(smem);

    const int tid  = threadIdx.x;
    const int lane = tid & 31;
    const int wid  = tid >> 5;
    const int wm   = wid >> 2;
    const int wn   = wid & 3;

    const int bx = blockIdx.x;           // 0..NFULL-1
    const int g  = bx / (MT * NT);
    const int r2 = bx % (MT * NT);
    const int mt = r2 / NT;
    const int nt = r2 % NT;

    const size_t m0 = (size_t)g * MG + (size_t)mt * TILE_M;
    const int    n0 = nt * TILE_J;

    const __half* Ax = x + m0 * HDIM;
    const __half* Wg = w + ((size_t)g * (2 * IDIM) + (size_t)n0) * HDIM;

    uint32_t dA[4], oA[4];
    #pragma unroll
    for (int t = 0; t < 4; ++t) {
        const int c = tid + THREADS * t;
        const int m = c >> 3, s = c & 7;
        dA[t] = (uint32_t)((((m >> 3) * 8 + s) << 7) + (((m & 7) ^ s) << 4));
        oA[t] = (uint32_t)(m * HDIM + s * 8);
    }
    uint32_t dB[8], oB[8];
    #pragma unroll
    for (int t = 0; t < 8; ++t) {
        const int c  = tid + THREADS * t;
        const int rr = c >> 3, s = c & 7;
        const int j  = rr >> 1;
        dB[t] = (uint32_t)(A_BYTES + (((rr >> 3) * 8 + s) << 7) + (((rr & 7) ^ s) << 4));
        oB[t] = (uint32_t)(j * HDIM + s * 8 + ((rr & 1) ? IDIM * HDIM : 0));
    }

    const int quad = lane >> 3;
    const int row  = lane & 7;
    const uint32_t mterm0 = (uint32_t)((wm * 8 + (quad & 1)) << 10);
    uint32_t ktA[4];
    #pragma unroll
    for (int ks = 0; ks < 4; ++ks) {
        const int kb = 2 * ks + (quad >> 1);
        ktA[ks] = (uint32_t)((kb << 7) + ((row ^ kb) << 4));
    }
    const uint32_t nterm0 = (uint32_t)(A_BYTES + ((wn * 8 + (quad >> 1)) << 10));
    uint32_t ktB[4];
    #pragma unroll
    for (int ks = 0; ks < 4; ++ks) {
        const int kb = 2 * ks + (quad & 1);
        ktB[ks] = (uint32_t)((kb << 7) + ((row ^ kb) << 4));
    }

    float acc[ACC_N];
    #pragma unroll
    for (int i = 0; i < ACC_N; ++i) acc[i] = 0.0f;

    #pragma unroll
    for (int s = 0; s < STAGES - 1; ++s) {
        const uint32_t st = sb + (uint32_t)(s * STAGE_BYTES);
        const __half* a = Ax + s * TILE_K;
        const __half* b = Wg + s * TILE_K;
        #pragma unroll
        for (int t = 0; t < 4; ++t) cp_async16(st + dA[t], a + oA[t]);
        #pragma unroll
        for (int t = 0; t < 8; ++t) cp_async16(st + dB[t], b + oB[t]);
        cp_commit();
    }

    #pragma unroll 1
    for (int i = 0; i < NITER; ++i) {
        cp_wait1();
        __syncthreads();

        if (i + STAGES - 1 < NITER) {
            const int it = i + STAGES - 1;
            const uint32_t stw = sb + (uint32_t)((it & 3) * STAGE_BYTES);
            const __half* a = Ax + it * TILE_K;
            const __half* b = Wg + it * TILE_K;
            #pragma unroll
            for (int t = 0; t < 4; ++t) cp_async16(stw + dA[t], a + oA[t]);
            #pragma unroll
            for (int t = 0; t < 8; ++t) cp_async16(stw + dB[t], b + oB[t]);
        }
        cp_commit();

        const uint32_t st = sb + (uint32_t)((i & 3) * STAGE_BYTES);
        #pragma unroll
        for (int ks = 0; ks < 4; ++ks) {
            uint32_t afr[16], bfr[16];
            #pragma unroll
            for (int f = 0; f < 4; ++f)
                ldsm4(&afr[4 * f], st + mterm0 + (uint32_t)(f << 11) + ktA[ks]);
            #pragma unroll
            for (int gg = 0; gg < 4; ++gg)
                ldsm4(&bfr[4 * gg], st + nterm0 + (uint32_t)(gg << 11) + ktB[ks]);
            #pragma unroll
            for (int f = 0; f < 4; ++f) {
                #pragma unroll
                for (int nf = 0; nf < 8; ++nf) {
                    const int bo = ((nf >> 1) << 2) + ((nf & 1) << 1);
                    mma16(&acc[(f * 8 + nf) * 4], &afr[4 * f], bfr[bo], bfr[bo + 1]);
                }
            }
        }
    }

    __syncthreads();

    const int gid = lane >> 2;
    const int tg  = lane & 3;
    #pragma unroll
    for (int f = 0; f < 4; ++f) {
        #pragma unroll
        for (int nf = 0; nf < 8; ++nf) {
            const float* c = &acc[(f * 8 + nf) * 4];
            const size_t mg1 = m0 + (size_t)(wm * 64 + f * 16 + gid);
            const int    jg  = n0 + wn * 32 + nf * 4 + tg;
            out[mg1 * IDIM + jg]       = silu_mul(c[0], c[1]);
            out[(mg1 + 8) * IDIM + jg] = silu_mul(c[2], c[3]);
        }
    }
}

// ---------------- TAIL kernel: half-K CTAs for the last 56 tiles ----------------
static constexpr int TITER = NITER / 2;       // 32

__global__ void __launch_bounds__(THREADS, 1)
swiglu_tail(const __half* __restrict__ x, const __half* __restrict__ w) {
    extern __shared__ char smem[];
    const uint32_t sb = smem_u32(smem);

    const int tid  = threadIdx.x;
    const int lane = tid & 31;
    const int wid  = tid >> 5;
    const int wm   = wid >> 2;
    const int wn   = wid & 3;

    const int sp      = blockIdx.x;      // 0..111
    const int tileIdx = NFULL + (sp >> 1);
    const int k0      = (sp & 1) * TITER;

    const int g  = tileIdx / (MT * NT);
    const int r2 = tileIdx % (MT * NT);
    const int mt = r2 / NT;
    const int nt = r2 % NT;

    const size_t m0 = (size_t)g * MG + (size_t)mt * TILE_M;
    const int    n0 = nt * TILE_J;

    const __half* Ax = x + m0 * HDIM + (size_t)k0 * TILE_K;
    const __half* Wg = w + ((size_t)g * (2 * IDIM) + (size_t)n0) * HDIM + (size_t)k0 * TILE_K;

    uint32_t dA[4], oA[4];
    #pragma unroll
    for (int t = 0; t < 4; ++t) {
        const int c = tid + THREADS * t;
        const int m = c >> 3, s = c & 7;
        dA[t] = (uint32_t)((((m >> 3) * 8 + s) << 7) + (((m & 7) ^ s) << 4));
        oA[t] = (uint32_t)(m * HDIM + s * 8);
    }
    uint32_t dB[8], oB[8];
    #pragma unroll
    for (int t = 0; t < 8; ++t) {
        const int c  = tid + THREADS * t;
        const int rr = c >> 3, s = c & 7;
        const int j  = rr >> 1;
        dB[t] = (uint32_t)(A_BYTES + (((rr >> 3) * 8 + s) << 7) + (((rr & 7) ^ s) << 4));
        oB[t] = (uint32_t)(j * HDIM + s * 8 + ((rr & 1) ? IDIM * HDIM : 0));
    }

    const int quad = lane >> 3;
    const int row  = lane & 7;
    const uint32_t mterm0 = (uint32_t)((wm * 8 + (quad & 1)) << 10);
    uint32_t ktA[4];
    #pragma unroll
    for (int ks = 0; ks < 4; ++ks) {
        const int kb = 2 * ks + (quad >> 1);
        ktA[ks] = (uint32_t)((kb << 7) + ((row ^ kb) << 4));
    }
    const uint32_t nterm0 = (uint32_t)(A_BYTES + ((wn * 8 + (quad >> 1)) << 10));
    uint32_t ktB[4];
    #pragma unroll
    for (int ks = 0; ks < 4; ++ks) {
        const int kb = 2 * ks + (quad & 1);
        ktB[ks] = (uint32_t)((kb << 7) + ((row ^ kb) << 4));
    }

    float acc[ACC_N];
    #pragma unroll
    for (int i = 0; i < ACC_N; ++i) acc[i] = 0.0f;

    #pragma unroll
    for (int s = 0; s < STAGES - 1; ++s) {
        const uint32_t st = sb + (uint32_t)(s * STAGE_BYTES);
        const __half* a = Ax + s * TILE_K;
        const __half* b = Wg + s * TILE_K;
        #pragma unroll
        for (int t = 0; t < 4; ++t) cp_async16(st + dA[t], a + oA[t]);
        #pragma unroll
        for (int t = 0; t < 8; ++t) cp_async16(st + dB[t], b + oB[t]);
        cp_commit();
    }

    #pragma unroll 1
    for (int i = 0; i < TITER; ++i) {
        cp_wait1();
        __syncthreads();

        if (i + STAGES - 1 < TITER) {
            const int it = i + STAGES - 1;
            const uint32_t stw = sb + (uint32_t)((it & 3) * STAGE_BYTES);
            const __half* a = Ax + it * TILE_K;
            const __half* b = Wg + it * TILE_K;
            #pragma unroll
            for (int t = 0; t < 4; ++t) cp_async16(stw + dA[t], a + oA[t]);
            #pragma unroll
            for (int t = 0; t < 8; ++t) cp_async16(stw + dB[t], b + oB[t]);
        }
        cp_commit();

        const uint32_t st = sb + (uint32_t)((i & 3) * STAGE_BYTES);
        #pragma unroll
        for (int ks = 0; ks < 4; ++ks) {
            uint32_t afr[16], bfr[16];
            #pragma unroll
            for (int f = 0; f < 4; ++f)
                ldsm4(&afr[4 * f], st + mterm0 + (uint32_t)(f << 11) + ktA[ks]);
            #pragma unroll
            for (int gg = 0; gg < 4; ++gg)
                ldsm4(&bfr[4 * gg], st + nterm0 + (uint32_t)(gg << 11) + ktB[ks]);
            #pragma unroll
            for (int f = 0; f < 4; ++f) {
                #pragma unroll
                for (int nf = 0; nf < 8; ++nf) {
                    const int bo = ((nf >> 1) << 2) + ((nf & 1) << 1);
                    mma16(&acc[(f * 8 + nf) * 4], &afr[4 * f], bfr[bo], bfr[bo + 1]);
                }
            }
        }
    }

    __syncthreads();

    float* dst = g_part + ((size_t)(sp & 1) * NSPLIT + (size_t)(sp >> 1)) *
                         (THREADS * ACC_N) + (size_t)tid * ACC_N;
    #pragma unroll
    for (int i = 0; i < ACC_N; ++i) dst[i] = acc[i];
}

// ---------------- combine: flat, coalesced; one output element per thread ----------------
static constexpr int PAIRS_PER_TILE = THREADS * ACC_N / 2;   // 16384
static constexpr int NPAIRS = NSPLIT * PAIRS_PER_TILE;       // 917504

__global__ void __launch_bounds__(256, 1)
combine_kernel(float* __restrict__ out) {
    const int j = blockIdx.x * 256 + threadIdx.x;
    if (j >= NPAIRS) return;

    const int sp2 = j >> 14;                 // / PAIRS_PER_TILE
    const int rem = j & (PAIRS_PER_TILE - 1);
    const int tid = rem >> 6;                // / (ACC_N/2)
    const int a   = rem & 63;

    const size_t off = (size_t)sp2 * (THREADS * ACC_N) + (size_t)tid * ACC_N + 2 * a;
    const float2 v0 = *reinterpret_cast<const float2*>(g_part + off);
    const float2 v1 = *reinterpret_cast<const float2*>(
        g_part + (size_t)NSPLIT * (THREADS * ACC_N) + off);
    const float gv = v0.x + v1.x;
    const float uv = v0.y + v1.y;

    const int lane = tid & 31, wid = tid >> 5;
    const int wm = wid >> 2, wn = wid & 3;
    const int gid = lane >> 2, tg = lane & 3;
    const int half = a & 1, fn = a >> 1;
    const int f = fn >> 3, nf = fn & 7;

    const int tileIdx = NFULL + sp2;
    const int g  = tileIdx / (MT * NT);
    const int r2 = tileIdx % (MT * NT);
    const int mt = r2 / NT;
    const int nt = r2 % NT;
    const size_t m0 = (size_t)g * MG + (size_t)mt * TILE_M;
    const int    n0 = nt * TILE_J;

    const size_t mg1 = m0 + (size_t)(wm * 64 + f * 16 + gid + half * 8);
    const int    jg  = n0 + wn * 32 + nf * 4 + tg;
    out[mg1 * IDIM + jg] = silu_mul(gv, uv);
}

// ---------------- launch ----------------
extern "C" void kernel_launch(void* const* d_in, const int* in_sizes, int n_in,
                              void* d_out, int out_size) {
    const float* x = (const float*)d_in[0];
    const float* w = (const float*)d_in[1];
    float* out = (float*)d_out;

    void* pxh = nullptr;
    void* pwh = nullptr;
    cudaGetSymbolAddress(&pxh, g_xh);
    cudaGetSymbolAddress(&pwh, g_wh);

    cvt_f16_kernel<<<NT8 / 256, 256>>>((const float4*)x, (__half*)pxh,
                                       (const float4*)w, (__half*)pwh);

    cudaFuncSetAttribute(swiglu_full,
                         cudaFuncAttributeMaxDynamicSharedMemorySize, SMEM_TOTAL);
    cudaFuncSetAttribute(swiglu_tail,
                         cudaFuncAttributeMaxDynamicSharedMemorySize, SMEM_TOTAL);

    swiglu_full<<<NFULL, THREADS, SMEM_TOTAL>>>((const __half*)pxh, (const __half*)pwh, out);
    swiglu_tail<<<2 * NSPLIT, THREADS, SMEM_TOTAL>>>((const __half*)pxh, (const __half*)pwh);
    combine_kernel<<<(NPAIRS + 255) / 256, 256>>>(out);
}